// round 9
// baseline (speedup 1.0000x reference)
#include <cuda_runtime.h>
#include <cuda_bf16.h>
#include <cstdint>

#define N_NODES 100000
#define N_EDGES 1000000
#define IN_CH   128
#define OUT_CH  128
#define T_DIM   64
#define AGG_W   192

// ---------------- device scratch ----------------
__device__ __align__(16) float g_agg[(size_t)N_NODES * AGG_W];
__device__ __align__(16) float g_deg[N_NODES];
__device__ __align__(16) float g_cb[128];         // W_T_b + T_b
__device__ int g_idx_is64;

// ---------------- generic helpers ----------------
__device__ __forceinline__ void red_add_v4(float* p, float4 v) {
    unsigned long long gp = __cvta_generic_to_global((void*)p);
    asm volatile("red.global.add.v4.f32 [%0], {%1,%2,%3,%4};"
                 :: "l"(gp), "f"(v.x), "f"(v.y), "f"(v.z), "f"(v.w)
                 : "memory");
}
__device__ __forceinline__ uint32_t smem_u32(const void* p) {
    uint32_t a;
    asm("{ .reg .u64 t; cvta.to.shared.u64 t, %1; cvt.u32.u64 %0, t; }"
        : "=r"(a) : "l"(p));
    return a;
}
#define SW128(o) ((o) ^ (((o) >> 3) & 0x70))

__device__ __forceinline__ void ldmx4(uint32_t addr, uint32_t& r0, uint32_t& r1,
                                      uint32_t& r2, uint32_t& r3) {
    asm volatile("ldmatrix.sync.aligned.m8n8.x4.shared.b16 {%0,%1,%2,%3}, [%4];"
                 : "=r"(r0), "=r"(r1), "=r"(r2), "=r"(r3) : "r"(addr));
}
__device__ __forceinline__ void mma_bf16(float* c, const uint32_t* a, const uint32_t* b) {
    asm volatile("mma.sync.aligned.m16n8k16.row.col.f32.bf16.bf16.f32 "
                 "{%0,%1,%2,%3}, {%4,%5,%6,%7}, {%8,%9}, {%0,%1,%2,%3};"
                 : "+f"(c[0]), "+f"(c[1]), "+f"(c[2]), "+f"(c[3])
                 : "r"(a[0]), "r"(a[1]), "r"(a[2]), "r"(a[3]), "r"(b[0]), "r"(b[1]));
}

// ---------------- kernel 0: detect edge_index dtype ----------------
__global__ void detect_kernel(const int* __restrict__ ei_raw) {
    __shared__ int any_nonzero;
    if (threadIdx.x == 0) any_nonzero = 0;
    __syncthreads();
    for (int i = threadIdx.x; i < 4096; i += blockDim.x)
        if (ei_raw[2 * i + 1] != 0) any_nonzero = 1;
    __syncthreads();
    if (threadIdx.x == 0) g_idx_is64 = (any_nonzero == 0);
}
__device__ __forceinline__ int load_idx(const void* ei_raw, size_t pos) {
    if (g_idx_is64) return (int)__ldg(&((const long long*)ei_raw)[pos]);
    return __ldg(&((const int*)ei_raw)[pos]);
}

// ---------------- kernel 1: combined bias ----------------
__global__ void prep_kernel(const float* __restrict__ Wtb, const float* __restrict__ Tb) {
    int tid = threadIdx.x;
    if (tid < 128) g_cb[tid] = Wtb[tid] + Tb[tid];
}

// ---------------- kernel 2: zero accumulators ----------------
__global__ void zero_kernel() {
    const size_t n4_agg = (size_t)N_NODES * AGG_W / 4;
    const size_t n4_deg = N_NODES / 4;
    float4 z = make_float4(0.f, 0.f, 0.f, 0.f);
    size_t stride = (size_t)gridDim.x * blockDim.x;
    for (size_t i = blockIdx.x * (size_t)blockDim.x + threadIdx.x; i < n4_agg; i += stride)
        ((float4*)g_agg)[i] = z;
    for (size_t i = blockIdx.x * (size_t)blockDim.x + threadIdx.x; i < n4_deg; i += stride)
        ((float4*)g_deg)[i] = z;
}

// ---------------- kernel 3: merged edge scatter (role-split blocks) ----------
// blocks [0, GX): x scatter (LTS-bound). blocks [GX, GX+GT): tf scatter (DRAM).
#define GX_BLOCKS (N_EDGES / 64)   // 8 warps x 8 edges
#define GT_BLOCKS (N_EDGES / 64)

__global__ void edge_kernel(const void* __restrict__ ei_raw,
                            const float* __restrict__ x,
                            const float* __restrict__ tf) {
    int lane = threadIdx.x & 31;
    if (blockIdx.x < GX_BLOCKS) {
        // ----- x scatter: 8 edges/warp -----
        int warp = (blockIdx.x * blockDim.x + threadIdx.x) >> 5;
        size_t e0 = (size_t)warp * 8;
        if (e0 >= N_EDGES) return;

        int v = 0;
        if (lane < 8)       v = load_idx(ei_raw, e0 + lane);
        else if (lane < 16) v = load_idx(ei_raw, (size_t)N_EDGES + e0 + (lane - 8));

        int rows[8], cols[8];
#pragma unroll
        for (int i = 0; i < 8; i++) {
            rows[i] = __shfl_sync(0xffffffffu, v, i);
            cols[i] = __shfl_sync(0xffffffffu, v, 8 + i);
        }
        float4 vx[8];
#pragma unroll
        for (int i = 0; i < 8; i++) {
            int c = ((unsigned)cols[i] < N_NODES) ? cols[i] : 0;
            vx[i] = __ldg(&((const float4*)(x + (size_t)c * IN_CH))[lane]);
        }
#pragma unroll
        for (int i = 0; i < 8; i++) {
            if ((unsigned)rows[i] >= N_NODES || (unsigned)cols[i] >= N_NODES) continue;
            red_add_v4(g_agg + (size_t)rows[i] * AGG_W + lane * 4, vx[i]);
        }
        if (lane < 8 && (unsigned)rows[lane] < N_NODES)
            atomicAdd(&g_deg[rows[lane]], 1.0f);
    } else {
        // ----- tf scatter: 8 edges/warp, half-warp per edge, MLP=4 -----
        int warp = ((blockIdx.x - GX_BLOCKS) * blockDim.x + threadIdx.x) >> 5;
        size_t e0 = (size_t)warp * 8;
        if (e0 >= N_EDGES) return;
        int half = lane >> 4;
        int l = lane & 15;

        int v = 0;
        if (lane < 8) v = load_idx(ei_raw, e0 + lane);
        int rows[4];
        size_t edges[4];
#pragma unroll
        for (int p = 0; p < 4; p++) {
            edges[p] = e0 + 2 * p + half;
            rows[p] = __shfl_sync(0xffffffffu, v, 2 * p + half);
        }
        float4 vt[4];
#pragma unroll
        for (int p = 0; p < 4; p++)
            vt[p] = __ldg(&((const float4*)tf)[edges[p] * (T_DIM / 4) + l]);
#pragma unroll
        for (int p = 0; p < 4; p++) {
            if ((unsigned)rows[p] >= N_NODES) continue;
            red_add_v4(g_agg + (size_t)rows[p] * AGG_W + IN_CH + l * 4, vt[p]);
        }
    }
}

// ---------------- kernel 4: mma.sync GEMM, 512 threads, double-buffered -------
// C[100000][128] = relu( A[100000][320] @ B^T + Wsb + deg * cb )
#define KCH 64
#define NCHUNK 5
#define BUF_SZ 65536          // AHI|ALO|BHI|BLO, 16KB each
#define SMEM_SZ (2 * BUF_SZ)

__device__ __forceinline__ void cvt_split2(float a, float b, uint32_t& h, uint32_t& l) {
    __nv_bfloat162 hb = __floats2bfloat162_rn(a, b);
    float2 hf = __bfloat1622float2(hb);
    __nv_bfloat162 lb = __floats2bfloat162_rn(a - hf.x, b - hf.y);
    h = *(uint32_t*)&hb;
    l = *(uint32_t*)&lb;
}

struct Stage { float4 a[4]; float4 b[4]; };  // per-thread (512 threads)

__device__ __forceinline__ void load_chunk(Stage& s, int c, int m0, int tid,
                                           const float* __restrict__ x,
                                           const float* __restrict__ Wsw,
                                           const float* __restrict__ Wtw,
                                           const float* __restrict__ Tw) {
    int gk0 = c * KCH;
#pragma unroll
    for (int it = 0; it < 2; it++) {
        int task = tid + it * 512;        // 1024 tasks: row m, 8-elem group gg
        int m = task >> 3, gg = task & 7;
        int node = m0 + m;
        int gk = gk0 + gg * 8;
        float4 v0 = make_float4(0, 0, 0, 0), v1 = v0;
        if (node < N_NODES) {
            const float* base = (gk < 128)
                ? (x + (size_t)node * IN_CH + gk)
                : (g_agg + (size_t)node * AGG_W + (gk - 128));
            v0 = __ldg((const float4*)base);
            v1 = __ldg((const float4*)(base + 4));
        }
        s.a[it * 2] = v0; s.a[it * 2 + 1] = v1;
    }
    const float* bbase; int bstride;
    if (c < 2)      { bbase = Wsw + c * 64;       bstride = 128; }
    else if (c < 4) { bbase = Wtw + (c - 2) * 64; bstride = 128; }
    else            { bbase = Tw;                 bstride = 64;  }
#pragma unroll
    for (int it = 0; it < 2; it++) {
        int task = tid + it * 512;
        int n = task >> 3, gg = task & 7;
        const float* p = bbase + (size_t)n * bstride + gg * 8;
        s.b[it * 2]     = __ldg((const float4*)p);
        s.b[it * 2 + 1] = __ldg((const float4*)(p + 4));
    }
}

__device__ __forceinline__ void store_chunk(const Stage& s, char* buf, int tid) {
#pragma unroll
    for (int it = 0; it < 2; it++) {
        int task = tid + it * 512;
        int m = task >> 3, gg = task & 7;
        uint32_t off = SW128((uint32_t)(m * 128 + gg * 16));
        float4 v0 = s.a[it * 2], v1 = s.a[it * 2 + 1];
        uint4 H, L;
        cvt_split2(v0.x, v0.y, H.x, L.x);
        cvt_split2(v0.z, v0.w, H.y, L.y);
        cvt_split2(v1.x, v1.y, H.z, L.z);
        cvt_split2(v1.z, v1.w, H.w, L.w);
        *(uint4*)(buf + off) = H;
        *(uint4*)(buf + 16384 + off) = L;
        v0 = s.b[it * 2]; v1 = s.b[it * 2 + 1];
        cvt_split2(v0.x, v0.y, H.x, L.x);
        cvt_split2(v0.z, v0.w, H.y, L.y);
        cvt_split2(v1.x, v1.y, H.z, L.z);
        cvt_split2(v1.z, v1.w, H.w, L.w);
        *(uint4*)(buf + 32768 + off) = H;
        *(uint4*)(buf + 49152 + off) = L;
    }
}

__global__ void __launch_bounds__(512, 1)
gemm_mma_kernel(const float* __restrict__ x,
                const float* __restrict__ Wsw, const float* __restrict__ Wtw,
                const float* __restrict__ Tw,  const float* __restrict__ Wsb,
                float* __restrict__ out) {
    extern __shared__ char smem[];
    const uint32_t sb = smem_u32(smem);
    const int tid = threadIdx.x;
    const int wid = tid >> 5;
    const int lane = tid & 31;
    const int m0 = blockIdx.x * 128;
    const int wm = (wid >> 3) * 64;   // 2 m-groups
    const int wn = (wid & 7) * 16;    // 8 n-groups
    const int g = lane >> 2;
    const int t = lane & 3;

    float acc[4][2][4];               // [m-tile][n-tile][4]
#pragma unroll
    for (int i = 0; i < 4; i++)
#pragma unroll
        for (int j = 0; j < 2; j++)
#pragma unroll
            for (int r = 0; r < 4; r++) acc[i][j][r] = 0.f;

    Stage st;
    load_chunk(st, 0, m0, tid, x, Wsw, Wtw, Tw);
    store_chunk(st, smem, tid);
    __syncthreads();

    for (int c = 0; c < NCHUNK; c++) {
        if (c + 1 < NCHUNK)
            load_chunk(st, c + 1, m0, tid, x, Wsw, Wtw, Tw);

        uint32_t base = sb + (c & 1) * BUF_SZ;
#pragma unroll
        for (int ks = 0; ks < 4; ks++) {
            int kk = ks * 16;
            uint32_t a_hi[4][4], a_lo[4][4];
#pragma unroll
            for (int mi = 0; mi < 4; mi++) {
                int mrow = wm + mi * 16;
                int r = mrow + (lane & 7) + ((lane & 8) ? 8 : 0);
                int kb = (kk + ((lane & 16) ? 8 : 0)) * 2;
                uint32_t off = SW128((uint32_t)(r * 128 + kb));
                ldmx4(base + off, a_hi[mi][0], a_hi[mi][1], a_hi[mi][2], a_hi[mi][3]);
                ldmx4(base + 16384 + off, a_lo[mi][0], a_lo[mi][1], a_lo[mi][2], a_lo[mi][3]);
            }
            uint32_t b_hi[2][2], b_lo[2][2];
            {
                int r = wn + (lane & 7) + ((lane & 16) ? 8 : 0);
                int kb = (kk + ((lane & 8) ? 8 : 0)) * 2;
                uint32_t off = SW128((uint32_t)(r * 128 + kb));
                uint32_t q0, q1, q2, q3;
                ldmx4(base + 32768 + off, q0, q1, q2, q3);
                b_hi[0][0] = q0; b_hi[0][1] = q1;
                b_hi[1][0] = q2; b_hi[1][1] = q3;
                ldmx4(base + 49152 + off, q0, q1, q2, q3);
                b_lo[0][0] = q0; b_lo[0][1] = q1;
                b_lo[1][0] = q2; b_lo[1][1] = q3;
            }
#pragma unroll
            for (int mi = 0; mi < 4; mi++)
#pragma unroll
                for (int ni = 0; ni < 2; ni++) {
                    mma_bf16(acc[mi][ni], a_hi[mi], b_hi[ni]);
                    mma_bf16(acc[mi][ni], a_lo[mi], b_hi[ni]);
                    mma_bf16(acc[mi][ni], a_hi[mi], b_lo[ni]);
                }
        }
        if (c + 1 < NCHUNK) {
            store_chunk(st, smem + ((c + 1) & 1) * BUF_SZ, tid);
            __syncthreads();
        }
    }

    // ---- epilogue: bias + deg*cb + relu, store ----
#pragma unroll
    for (int mi = 0; mi < 4; mi++) {
        int row0 = m0 + wm + mi * 16 + g;
        int row1 = row0 + 8;
        float d0 = (row0 < N_NODES) ? g_deg[row0] : 0.f;
        float d1 = (row1 < N_NODES) ? g_deg[row1] : 0.f;
#pragma unroll
        for (int ni = 0; ni < 2; ni++) {
            int cn = wn + ni * 8 + t * 2;
            float2 bs = *(const float2*)(Wsb + cn);
            float2 cb = *(const float2*)(g_cb + cn);
            if (row0 < N_NODES) {
                float2 o;
                o.x = fmaxf(acc[mi][ni][0] + bs.x + d0 * cb.x, 0.f);
                o.y = fmaxf(acc[mi][ni][1] + bs.y + d0 * cb.y, 0.f);
                *(float2*)(out + (size_t)row0 * OUT_CH + cn) = o;
            }
            if (row1 < N_NODES) {
                float2 o;
                o.x = fmaxf(acc[mi][ni][2] + bs.x + d1 * cb.x, 0.f);
                o.y = fmaxf(acc[mi][ni][3] + bs.y + d1 * cb.y, 0.f);
                *(float2*)(out + (size_t)row1 * OUT_CH + cn) = o;
            }
        }
    }
}

// ---------------- launcher ----------------
extern "C" void kernel_launch(void* const* d_in, const int* in_sizes, int n_in,
                              void* d_out, int out_size) {
    const float* x = nullptr; const void* ei = nullptr; const float* tf = nullptr;
    const float* Wsw = nullptr; const float* Wsb = nullptr;
    const float* Wtw = nullptr; const float* Wtb = nullptr;
    const float* Tw = nullptr;  const float* Tb = nullptr;
    int n16384 = 0, n128 = 0;
    for (int i = 0; i < n_in; i++) {
        long long s = in_sizes[i];
        void* p = d_in[i];
        if (s == (long long)N_NODES * IN_CH)      x  = (const float*)p;
        else if (s == 2LL * N_EDGES)              ei = (const void*)p;
        else if (s == (long long)N_EDGES * T_DIM) tf = (const float*)p;
        else if (s == OUT_CH * T_DIM)             Tw = (const float*)p;
        else if (s == OUT_CH * IN_CH) {
            if (n16384++ == 0) Wsw = (const float*)p; else Wtw = (const float*)p;
        } else if (s == OUT_CH) {
            if (n128 == 0) Wsb = (const float*)p;
            else if (n128 == 1) Wtb = (const float*)p;
            else Tb = (const float*)p;
            n128++;
        }
    }
    float* out = (float*)d_out;

    cudaFuncSetAttribute(gemm_mma_kernel,
                         cudaFuncAttributeMaxDynamicSharedMemorySize, SMEM_SZ);

    detect_kernel<<<1, 256>>>((const int*)ei);
    prep_kernel<<<1, 128>>>(Wtb, Tb);
    zero_kernel<<<2048, 256>>>();
    edge_kernel<<<GX_BLOCKS + GT_BLOCKS, 256>>>(ei, x, tf);
    gemm_mma_kernel<<<(N_NODES + 127) / 128, 512, SMEM_SZ>>>(x, Wsw, Wtw, Tw, Wsb, out);
}